// round 5
// baseline (speedup 1.0000x reference)
#include <cuda_runtime.h>
#include <cstdint>

// Problem constants
#define BB   512
#define SS   1024
#define INW  32
#define HH   128
#define GG   512          // 4*H
#define KK   160          // H + IN
#define RR   4            // batch rows per CTA
#define NBLK 128          // 512 / RR
#define NTHR 512          // 16 warps: warp = (pair p, khalf); thread = 2 gates x 1 k-half x 4 rows
#define KHALF 80          // k per half
#define WREG 32           // weight floats per (gate, k-half) in registers (8 quads)
#define WSMH 48           // weight floats per (gate, k-half) in smem (12 quads)
#define WSTRIDE 100       // 96 + 4 pad; lane stride 100 mod 32 = 4 -> LDS.128 conflict-free

#define W_SH_FLOATS (GG * WSTRIDE)                       // 51200
#define HX_FLOATS   (RR * KK)                            // 640: per row 0..127 = h, 128..159 = x
#define GP_FLOATS   (2 * RR * GG)                        // 4096 partial-sum buffer
#define SMEM_FLOATS (W_SH_FLOATS + HX_FLOATS + GP_FLOATS)
#define SMEM_BYTES  (SMEM_FLOATS * 4)                    // 223744 B < 232448 cap

// Packed fp32x2 FMA (Blackwell; ptxas never emits it from C++)
__device__ __forceinline__ unsigned long long ffma2(unsigned long long a,
                                                    unsigned long long b,
                                                    unsigned long long c) {
    unsigned long long d;
    asm("fma.rn.f32x2 %0, %1, %2, %3;" : "=l"(d) : "l"(a), "l"(b), "l"(c));
    return d;
}

__device__ __forceinline__ void unpack2(unsigned long long v, float& lo, float& hi) {
    asm("mov.b64 {%0, %1}, %2;" : "=f"(lo), "=f"(hi) : "l"(v));
}

__device__ __forceinline__ float sigmoid_f(float v) {
    return __fdividef(1.0f, 1.0f + __expf(-v));
}
__device__ __forceinline__ float tanh_f(float v) {
    return 1.0f - __fdividef(2.0f, __expf(2.0f * v) + 1.0f);
}

__global__ void __launch_bounds__(NTHR, 1)
lstm_fused_kernel(const float* __restrict__ x,     // [B,S,IN]
                  const float* __restrict__ Wih,   // [4H,IN]
                  const float* __restrict__ Whh,   // [4H,H]
                  const float* __restrict__ bih,   // [4H]
                  const float* __restrict__ bhh,   // [4H]
                  const float* __restrict__ Wlin,  // [1, S*H]
                  const float* __restrict__ blin,  // [1]
                  float* __restrict__ out)         // [B,1]
{
    extern __shared__ float sm[];
    float* w_sh = sm;                              // [512][WSTRIDE]: [g][kh*48 + i]
    float* hx   = sm + W_SH_FLOATS;                // [RR][160]
    float* gp   = hx + HX_FLOATS;                  // [2][RR][512] partial sums

    const int tid  = threadIdx.x;
    const int wid  = tid >> 5;
    const int lane = tid & 31;
    const int p    = wid >> 1;                     // gate pair-group 0..7
    const int kh   = wid & 1;                      // k-half of this warp
    const int ga   = p * 32 + lane;                // first gate row (0..255)
    const int gb   = ga + 256;                     // second gate row
    const int koff = kh * KHALF;                   // operand k offset
    const int b0   = blockIdx.x * RR;

    // ---- Prologue ----
    // Register weights: Whh[g][koff .. koff+32) for both gates (8 quads each)
    unsigned long long wA[16], wB[16];
    {
        const ulonglong2* pa = reinterpret_cast<const ulonglong2*>(Whh + (size_t)ga * HH + koff);
        const ulonglong2* pb = reinterpret_cast<const ulonglong2*>(Whh + (size_t)gb * HH + koff);
        #pragma unroll
        for (int i = 0; i < 8; i++) {
            ulonglong2 v = pa[i]; wA[2 * i] = v.x; wA[2 * i + 1] = v.y;
            ulonglong2 w = pb[i]; wB[2 * i] = w.x; wB[2 * i + 1] = w.y;
        }
    }

    // smem weights: per (gate, khalf): k = kh*80 + 32 .. kh*80 + 80
    for (int idx = tid; idx < GG * 96; idx += NTHR) {
        int g = idx / 96, rem = idx % 96;
        int fkh = rem / WSMH, i = rem % WSMH;
        int k = fkh * KHALF + WREG + i;
        float v = (k < HH) ? Whh[(size_t)g * HH + k]
                           : Wih[(size_t)g * INW + (k - HH)];
        w_sh[g * WSTRIDE + fkh * WSMH + i] = v;
    }
    // Zero hx, barrier, then x(t=0) (avoid R3 race)
    for (int idx = tid; idx < HX_FLOATS; idx += NTHR) hx[idx] = 0.0f;
    __syncthreads();
    if (tid < RR * INW) {
        int rr = tid >> 5, ii = tid & 31;
        hx[rr * KK + HH + ii] = x[(size_t)(b0 + rr) * SS * INW + ii];
    }

    // elementwise role: one hidden unit (r_ew, j) per thread
    const int j    = tid & (HH - 1);
    const int r_ew = tid >> 7;                     // 0..3
    // biases for the 4 gates of unit j (added in elementwise phase)
    const float bi = bih[j]            + bhh[j];
    const float bf = bih[j + HH]       + bhh[j + HH];
    const float bg = bih[j + 2 * HH]   + bhh[j + 2 * HH];
    const float bo = bih[j + 3 * HH]   + bhh[j + 3 * HH];
    float c_state = 0.0f;
    float lin_acc = 0.0f;

    __syncthreads();

    const ulonglong2* wpa = reinterpret_cast<const ulonglong2*>(w_sh + ga * WSTRIDE + kh * WSMH);
    const ulonglong2* wpb = reinterpret_cast<const ulonglong2*>(w_sh + gb * WSTRIDE + kh * WSMH);

    // ---- Main sequential loop over timesteps ----
    #pragma unroll 1
    for (int t = 0; t < SS; t++) {
        // Early global loads (latency hidden under the gate GEMM)
        float wl = __ldg(Wlin + (size_t)t * HH + j);
        float xr = 0.0f;
        if (tid < RR * INW) {
            int rr = tid >> 5, ii = tid & 31;
            int tn = (t + 1 < SS) ? (t + 1) : t;
            xr = x[(size_t)(b0 + rr) * SS * INW + (size_t)tn * INW + ii];
        }

        // === Gate phase: 2 gates x 4 rows x this warp's k-half ===
        unsigned long long aA[RR], aB[RR];
        #pragma unroll
        for (int r = 0; r < RR; r++) { aA[r] = 0ull; aB[r] = 0ull; }

        // quads 0..7: register-resident weights
        #pragma unroll
        for (int q = 0; q < 8; q++) {
            #pragma unroll
            for (int r = 0; r < RR; r++) {
                ulonglong2 h4 = *reinterpret_cast<const ulonglong2*>(hx + r * KK + koff + 4 * q);
                aA[r] = ffma2(wA[2 * q],     h4.x, aA[r]);
                aA[r] = ffma2(wA[2 * q + 1], h4.y, aA[r]);
                aB[r] = ffma2(wB[2 * q],     h4.x, aB[r]);
                aB[r] = ffma2(wB[2 * q + 1], h4.y, aB[r]);
            }
        }
        // quads 8..19: smem weights
        #pragma unroll
        for (int q = 0; q < 12; q++) {
            ulonglong2 wa = wpa[q];
            ulonglong2 wb = wpb[q];
            #pragma unroll
            for (int r = 0; r < RR; r++) {
                ulonglong2 h4 = *reinterpret_cast<const ulonglong2*>(hx + r * KK + koff + WREG + 4 * q);
                aA[r] = ffma2(wa.x, h4.x, aA[r]);
                aA[r] = ffma2(wa.y, h4.y, aA[r]);
                aB[r] = ffma2(wb.x, h4.x, aB[r]);
                aB[r] = ffma2(wb.y, h4.y, aB[r]);
            }
        }
        // write partial sums (raw, biases added in elementwise phase)
        #pragma unroll
        for (int r = 0; r < RR; r++) {
            float lo, hi;
            unpack2(aA[r], lo, hi);
            gp[(kh * RR + r) * GG + ga] = lo + hi;
            unpack2(aB[r], lo, hi);
            gp[(kh * RR + r) * GG + gb] = lo + hi;
        }
        __syncthreads();

        // === Elementwise phase: one hidden unit per thread ===
        {
            const float* g0 = gp + r_ew * GG;             // khalf 0 partials
            const float* g1 = gp + (RR + r_ew) * GG;      // khalf 1 partials
            float pi = g0[j]          + g1[j]          + bi;
            float pf = g0[j + HH]     + g1[j + HH]     + bf;
            float pg = g0[j + 2 * HH] + g1[j + 2 * HH] + bg;
            float po = g0[j + 3 * HH] + g1[j + 3 * HH] + bo;

            float iv = sigmoid_f(pi);
            float fv = sigmoid_f(pf);
            float gv = tanh_f(pg);
            float ov = sigmoid_f(po);
            c_state = fmaf(fv, c_state, iv * gv);
            float hv = ov * tanh_f(c_state);
            hx[r_ew * KK + j] = hv;
            lin_acc = fmaf(hv, wl, lin_acc);
        }
        // publish prefetched x for t+1
        if (tid < RR * INW) {
            int rr = tid >> 5, ii = tid & 31;
            hx[rr * KK + HH + ii] = xr;
        }
        __syncthreads();
    }

    // ---- Epilogue: reduce fused-linear accumulators ----
    // warp wid covers row (wid>>2), j-block (wid&3)
    float v = lin_acc;
    #pragma unroll
    for (int off = 16; off; off >>= 1) v += __shfl_xor_sync(0xffffffffu, v, off);
    if (lane == 0) gp[wid] = v;                    // 16 warp partials
    __syncthreads();
    if (tid < RR) {
        float s = gp[4 * tid] + gp[4 * tid + 1] + gp[4 * tid + 2] + gp[4 * tid + 3];
        out[b0 + tid] = s + blin[0];
    }
}

extern "C" void kernel_launch(void* const* d_in, const int* in_sizes, int n_in,
                              void* d_out, int out_size)
{
    const float* x    = (const float*)d_in[0];
    const float* Wih  = (const float*)d_in[1];
    const float* Whh  = (const float*)d_in[2];
    const float* bih  = (const float*)d_in[3];
    const float* bhh  = (const float*)d_in[4];
    const float* Wlin = (const float*)d_in[5];
    const float* blin = (const float*)d_in[6];
    float* out = (float*)d_out;

    cudaFuncSetAttribute(lstm_fused_kernel,
                         cudaFuncAttributeMaxDynamicSharedMemorySize, SMEM_BYTES);
    lstm_fused_kernel<<<NBLK, NTHR, SMEM_BYTES>>>(x, Wih, Whh, bih, bhh, Wlin, blin, out);
}

// round 7
// speedup vs baseline: 1.8361x; 1.8361x over previous
#include <cuda_runtime.h>
#include <cuda_bf16.h>
#include <cstdint>

// ---------------- problem constants ----------------
#define SS    1024
#define INW   32
#define HH    128
#define NTHR  256
#define NBLK  128          // 4 batch rows per CTA
#define KTOT  160          // 128 h + 32 x
#define NKT   10           // k16 tiles
#define BST   168          // B staging stride in bf16 (conflict-free)
#define BTERM (8 * BST * 2)        // 2688 B per term
#define GSTR  6                     // gbuf stride in floats (conflict-free)

#define OFF_ALO   0
#define ALO_BYTES (512 * KTOT * 2)          // 163840: W_lo in fragment order
#define OFF_B     ALO_BYTES                 // 2 terms x 8 n x BST bf16
#define OFF_GBUF  (OFF_B + 2 * BTERM)       // 169216: float[512][GSTR]
#define OFF_LRED  (OFF_GBUF + 512 * GSTR * 4)  // 181504
#define SMEM_BYTES (OFF_LRED + 256)         // 181760 < 227KB cap

// ---------------- helpers ----------------
__device__ __forceinline__ unsigned short bf16_bits(float v) {
    __nv_bfloat16 b = __float2bfloat16(v);
    return *reinterpret_cast<unsigned short*>(&b);
}
__device__ __forceinline__ float bf16_val(unsigned short s) {
    __nv_bfloat16 b = *reinterpret_cast<__nv_bfloat16*>(&s);
    return __bfloat162float(b);
}
// split w = hi + lo (both bf16); returns packed later by caller
__device__ __forceinline__ void split_bf16(float w, unsigned short& hi, unsigned short& lo) {
    hi = bf16_bits(w);
    lo = bf16_bits(w - bf16_val(hi));
}
__device__ __forceinline__ uint32_t pack2(unsigned short lo16, unsigned short hi16) {
    return (uint32_t)lo16 | ((uint32_t)hi16 << 16);   // low addr / low k in low bits
}

__device__ __forceinline__ void mma_bf16(float& d0, float& d1, float& d2, float& d3,
                                         uint32_t a0, uint32_t a1, uint32_t a2, uint32_t a3,
                                         uint32_t b0, uint32_t b1) {
    asm volatile(
        "mma.sync.aligned.m16n8k16.row.col.f32.bf16.bf16.f32 "
        "{%0,%1,%2,%3}, {%4,%5,%6,%7}, {%8,%9}, {%0,%1,%2,%3};"
        : "+f"(d0), "+f"(d1), "+f"(d2), "+f"(d3)
        : "r"(a0), "r"(a1), "r"(a2), "r"(a3), "r"(b0), "r"(b1));
}

__device__ __forceinline__ float sigmoid_f(float v) {
    return __fdividef(1.0f, 1.0f + __expf(-v));
}
__device__ __forceinline__ float tanh_f(float v) {
    return 1.0f - __fdividef(2.0f, __expf(2.0f * v) + 1.0f);
}

__global__ void __launch_bounds__(NTHR, 1)
lstm_mma_kernel(const float* __restrict__ x,     // [B,S,IN]
                const float* __restrict__ Wih,   // [4H,IN]
                const float* __restrict__ Whh,   // [4H,H]
                const float* __restrict__ bih,   // [4H]
                const float* __restrict__ bhh,   // [4H]
                const float* __restrict__ Wlin,  // [1, S*H]
                const float* __restrict__ blin,  // [1]
                float* __restrict__ out)         // [B,1]
{
    extern __shared__ char smc[];
    float* smf = reinterpret_cast<float*>(smc);
    const int tid  = threadIdx.x;
    const int wid  = tid >> 5;
    const int lane = tid & 31;
    const int b0   = blockIdx.x * 4;

    // ---------------- prologue ----------------
    // zero B staging + gbuf + lred
    for (int i = tid; i < (2 * BTERM) / 4; i += NTHR)
        reinterpret_cast<uint32_t*>(smc + OFF_B)[i] = 0;
    for (int i = tid; i < 512 * GSTR; i += NTHR)
        smf[(OFF_GBUF >> 2) + i] = 0.0f;
    if (tid < 64) smf[(OFF_LRED >> 2) + tid] = 0.0f;

    // Build W fragments: hi -> registers, lo -> smem in fragment order.
    // m-tile mt of warp wid covers gates wid*64 + mt*16 .. +15; gate row == MMA row.
    uint32_t wa[4][NKT][4];
    {
        const int r  = lane >> 2;
        const int kc = (lane & 3) * 2;
        #pragma unroll
        for (int mt = 0; mt < 4; mt++) {
            #pragma unroll
            for (int kt = 0; kt < NKT; kt++) {
                uint32_t lo4[4];
                #pragma unroll
                for (int rg = 0; rg < 4; rg++) {
                    int g = wid * 64 + mt * 16 + r + ((rg & 1) ? 8 : 0);
                    int k = kt * 16 + kc + ((rg & 2) ? 8 : 0);
                    float2 w2;
                    if (k < HH) w2 = *reinterpret_cast<const float2*>(Whh + (size_t)g * HH + k);
                    else        w2 = *reinterpret_cast<const float2*>(Wih + (size_t)g * INW + (k - HH));
                    unsigned short h0, l0, h1, l1;
                    split_bf16(w2.x, h0, l0);
                    split_bf16(w2.y, h1, l1);
                    wa[mt][kt][rg] = pack2(h0, h1);
                    lo4[rg]        = pack2(l0, l1);
                }
                uint4 v = make_uint4(lo4[0], lo4[1], lo4[2], lo4[3]);
                *reinterpret_cast<uint4*>(smc + OFF_ALO +
                    (size_t)((((wid * 4 + mt) * NKT + kt) * 32 + lane) * 16)) = v;
            }
        }
    }

    // ew role: thread owns units (j0, j0+1) of batch row n
    const int j0 = (tid >> 2) * 2;
    const int n  = tid & 3;
    const float bi0 = bih[j0]           + bhh[j0];
    const float bi1 = bih[j0 + 1]       + bhh[j0 + 1];
    const float bf0 = bih[j0 + 128]     + bhh[j0 + 128];
    const float bf1 = bih[j0 + 129]     + bhh[j0 + 129];
    const float bg0 = bih[j0 + 256]     + bhh[j0 + 256];
    const float bg1 = bih[j0 + 257]     + bhh[j0 + 257];
    const float bo0 = bih[j0 + 384]     + bhh[j0 + 384];
    const float bo1 = bih[j0 + 385]     + bhh[j0 + 385];
    float c0 = 0.0f, c1 = 0.0f;
    float lin = 0.0f;

    __syncthreads();                       // B staging zero complete
    // x(t=0) into staging (after the zero pass to avoid overwrite race)
    if (tid < 64) {
        int row = tid >> 4, i0 = (tid & 15) * 2;
        float2 xv = *reinterpret_cast<const float2*>(
            x + ((size_t)(b0 + row) * SS + 0) * INW + i0);
        unsigned short h0, l0, h1, l1;
        split_bf16(xv.x, h0, l0);
        split_bf16(xv.y, h1, l1);
        char* p = smc + OFF_B + (size_t)(row * BST + HH + i0) * 2;
        *reinterpret_cast<uint32_t*>(p)         = pack2(h0, h1);
        *reinterpret_cast<uint32_t*>(p + BTERM) = pack2(l0, l1);
    }
    __syncthreads();

    // B fragment address pieces (warp-uniform per lane)
    const int bn = lane >> 2;
    const int bk = (lane & 3) * 2;

    // ---------------- main recurrence ----------------
    #pragma unroll 1
    for (int t = 0; t < SS; t++) {
        // early independent global loads
        const float2 wl2 = __ldg(reinterpret_cast<const float2*>(
            Wlin + (size_t)t * HH + j0));
        float2 xv = make_float2(0.0f, 0.0f);
        if (tid < 64) {
            int row = tid >> 4, i0 = (tid & 15) * 2;
            int tn = (t + 1 < SS) ? (t + 1) : (SS - 1);
            xv = *reinterpret_cast<const float2*>(
                x + ((size_t)(b0 + row) * SS + tn) * INW + i0);
        }

        // === MMA phase: D[512,8] = Whi*Bhi + Whi*Blo + Wlo*Bhi ===
        float d0[4], d1[4], d2[4], d3[4];
        #pragma unroll
        for (int mt = 0; mt < 4; mt++) { d0[mt] = 0.f; d1[mt] = 0.f; d2[mt] = 0.f; d3[mt] = 0.f; }

        #pragma unroll
        for (int kt = 0; kt < NKT; kt++) {
            const char* bb = smc + OFF_B + (size_t)((bn * BST + kt * 16 + bk) * 2);
            uint32_t bh0 = *reinterpret_cast<const uint32_t*>(bb);
            uint32_t bh1 = *reinterpret_cast<const uint32_t*>(bb + 16);
            uint32_t bl0 = *reinterpret_cast<const uint32_t*>(bb + BTERM);
            uint32_t bl1 = *reinterpret_cast<const uint32_t*>(bb + BTERM + 16);
            #pragma unroll
            for (int mt = 0; mt < 4; mt++) {
                const uint4 alo = *reinterpret_cast<const uint4*>(smc + OFF_ALO +
                    (size_t)((((wid * 4 + mt) * NKT + kt) * 32 + lane) * 16));
                mma_bf16(d0[mt], d1[mt], d2[mt], d3[mt],
                         wa[mt][kt][0], wa[mt][kt][1], wa[mt][kt][2], wa[mt][kt][3],
                         bh0, bh1);
                mma_bf16(d0[mt], d1[mt], d2[mt], d3[mt],
                         wa[mt][kt][0], wa[mt][kt][1], wa[mt][kt][2], wa[mt][kt][3],
                         bl0, bl1);
                mma_bf16(d0[mt], d1[mt], d2[mt], d3[mt],
                         alo.x, alo.y, alo.z, alo.w,
                         bh0, bh1);
            }
        }
        // store D (batch cols 0..3 live in lanes with lane%4 < 2)
        if ((lane & 2) == 0) {
            const int c = (lane & 3) * 2;
            const int r = lane >> 2;
            #pragma unroll
            for (int mt = 0; mt < 4; mt++) {
                int gm = wid * 64 + mt * 16 + r;
                *reinterpret_cast<float2*>(smf + (OFF_GBUF >> 2) + gm * GSTR + c)
                    = make_float2(d0[mt], d1[mt]);
                *reinterpret_cast<float2*>(smf + (OFF_GBUF >> 2) + (gm + 8) * GSTR + c)
                    = make_float2(d2[mt], d3[mt]);
            }
        }
        __syncthreads();

        // === elementwise: units j0, j0+1 of row n ===
        {
            const float* gb = smf + (OFF_GBUF >> 2) + n;
            float pi0 = gb[(j0)       * GSTR] + bi0;
            float pi1 = gb[(j0 + 1)   * GSTR] + bi1;
            float pf0 = gb[(j0 + 128) * GSTR] + bf0;
            float pf1 = gb[(j0 + 129) * GSTR] + bf1;
            float pg0 = gb[(j0 + 256) * GSTR] + bg0;
            float pg1 = gb[(j0 + 257) * GSTR] + bg1;
            float po0 = gb[(j0 + 384) * GSTR] + bo0;
            float po1 = gb[(j0 + 385) * GSTR] + bo1;

            float iv0 = sigmoid_f(pi0), iv1 = sigmoid_f(pi1);
            float fv0 = sigmoid_f(pf0), fv1 = sigmoid_f(pf1);
            float gv0 = tanh_f(pg0),    gv1 = tanh_f(pg1);
            float ov0 = sigmoid_f(po0), ov1 = sigmoid_f(po1);
            c0 = fmaf(fv0, c0, iv0 * gv0);
            c1 = fmaf(fv1, c1, iv1 * gv1);
            float hv0 = ov0 * tanh_f(c0);
            float hv1 = ov1 * tanh_f(c1);
            lin = fmaf(hv0, wl2.x, fmaf(hv1, wl2.y, lin));

            unsigned short h0, l0, h1, l1;
            split_bf16(hv0, h0, l0);
            split_bf16(hv1, h1, l1);
            char* p = smc + OFF_B + (size_t)(n * BST + j0) * 2;
            *reinterpret_cast<uint32_t*>(p)         = pack2(h0, h1);
            *reinterpret_cast<uint32_t*>(p + BTERM) = pack2(l0, l1);
        }
        // x(t+1) into staging
        if (tid < 64) {
            int row = tid >> 4, i0 = (tid & 15) * 2;
            unsigned short h0, l0, h1, l1;
            split_bf16(xv.x, h0, l0);
            split_bf16(xv.y, h1, l1);
            char* p = smc + OFF_B + (size_t)(row * BST + HH + i0) * 2;
            *reinterpret_cast<uint32_t*>(p)         = pack2(h0, h1);
            *reinterpret_cast<uint32_t*>(p + BTERM) = pack2(l0, l1);
        }
        __syncthreads();
    }

    // ---------------- epilogue ----------------
    float v = lin;
    #pragma unroll
    for (int off = 4; off <= 16; off <<= 1) v += __shfl_xor_sync(0xffffffffu, v, off);
    if (lane < 4) smf[(OFF_LRED >> 2) + wid * 4 + lane] = v;   // lane == row n here
    __syncthreads();
    if (tid < 4) {
        float s = blin[0];
        #pragma unroll
        for (int w = 0; w < 8; w++) s += smf[(OFF_LRED >> 2) + w * 4 + tid];
        out[b0 + tid] = s;
    }
}

extern "C" void kernel_launch(void* const* d_in, const int* in_sizes, int n_in,
                              void* d_out, int out_size)
{
    const float* x    = (const float*)d_in[0];
    const float* Wih  = (const float*)d_in[1];
    const float* Whh  = (const float*)d_in[2];
    const float* bih  = (const float*)d_in[3];
    const float* bhh  = (const float*)d_in[4];
    const float* Wlin = (const float*)d_in[5];
    const float* blin = (const float*)d_in[6];
    float* out = (float*)d_out;

    cudaFuncSetAttribute(lstm_mma_kernel,
                         cudaFuncAttributeMaxDynamicSharedMemorySize, SMEM_BYTES);
    lstm_mma_kernel<<<NBLK, NTHR, SMEM_BYTES>>>(x, Wih, Whh, bih, bhh, Wlin, blin, out);
}